// round 2
// baseline (speedup 1.0000x reference)
#include <cuda_runtime.h>
#include <math.h>

// ---------------------------------------------------------------------------
// DecoderLayer: x -> self-attn(causal)+res+LN -> cross-attn+res+LN -> FFN+res+LN
// B=2, S=2048, d_model=1024, H=16, d_head=64, d_ff=4096, fp32.
// ---------------------------------------------------------------------------

#define DM     1024
#define DFF    4096
#define BATCH  2
#define SEQ    2048
#define NH     16
#define DH     64
#define MROWS  (BATCH * SEQ)   // 4096
#define LN_EPS 1e-5f

// ---- scratch (static __device__ arrays: allocation-free per harness rules) ----
__device__ float g_q [MROWS * DM];
__device__ float g_k [MROWS * DM];
__device__ float g_v [MROWS * DM];
__device__ float g_a [MROWS * DM];
__device__ float g_t [MROWS * DM];
__device__ float g_x1[MROWS * DM];
__device__ float g_x2[MROWS * DM];
__device__ float g_ff[(size_t)MROWS * DFF];

// ===========================================================================
// SGEMM: C[M,N] = A[M,K] @ W[N,K]^T + bias[N]  (both operands K-contiguous)
// mode 0: bias only; mode 1: bias + ReLU; mode 2: bias + residual add
// 128x128 tile, BK=16, 256 threads, 8x8 per thread.
// LDT = 132: row stride 528 bytes (multiple of 16) so float4 smem reads at
// any k row stay 16B-aligned (LDT=130 trapped with misaligned address).
// ===========================================================================
#define BM 128
#define BN 128
#define BK 16
#define LDT (BM + 4)

__global__ __launch_bounds__(256, 2)
void sgemm_kernel(const float* __restrict__ A,
                  const float* __restrict__ W,
                  const float* __restrict__ bias,
                  const float* __restrict__ res,
                  float* __restrict__ C,
                  int M, int N, int K, int mode)
{
    __shared__ float As[BK][LDT];
    __shared__ float Bs[BK][LDT];

    const int tid = threadIdx.x;
    const int tr  = tid >> 4;     // 0..15 (m group)
    const int tc  = tid & 15;     // 0..15 (n group)

    const float* Ablk = A + (size_t)blockIdx.y * BM * K;
    const float* Wblk = W + (size_t)blockIdx.x * BN * K;

    float acc[8][8];
#pragma unroll
    for (int i = 0; i < 8; i++)
#pragma unroll
        for (int j = 0; j < 8; j++) acc[i][j] = 0.f;

    for (int k0 = 0; k0 < K; k0 += BK) {
        // load tiles (transposed into [k][m]) — 2 float4 per thread per operand
#pragma unroll
        for (int t = 0; t < 2; t++) {
            int v   = tid + t * 256;
            int row = v >> 2;
            int c4  = (v & 3) << 2;
            float4 a = *(const float4*)(Ablk + (size_t)row * K + k0 + c4);
            As[c4+0][row] = a.x; As[c4+1][row] = a.y;
            As[c4+2][row] = a.z; As[c4+3][row] = a.w;
            float4 b = *(const float4*)(Wblk + (size_t)row * K + k0 + c4);
            Bs[c4+0][row] = b.x; Bs[c4+1][row] = b.y;
            Bs[c4+2][row] = b.z; Bs[c4+3][row] = b.w;
        }
        __syncthreads();

#pragma unroll
        for (int k = 0; k < BK; k++) {
            float a[8], b[8];
            *(float4*)(a)     = *(const float4*)&As[k][tr * 8];
            *(float4*)(a + 4) = *(const float4*)&As[k][tr * 8 + 4];
            *(float4*)(b)     = *(const float4*)&Bs[k][tc * 8];
            *(float4*)(b + 4) = *(const float4*)&Bs[k][tc * 8 + 4];
#pragma unroll
            for (int i = 0; i < 8; i++)
#pragma unroll
                for (int j = 0; j < 8; j++)
                    acc[i][j] += a[i] * b[j];
        }
        __syncthreads();
    }

    // epilogue
    const int m0 = blockIdx.y * BM + tr * 8;
    const int n0 = blockIdx.x * BN + tc * 8;
    float4 bv0 = *(const float4*)(bias + n0);
    float4 bv1 = *(const float4*)(bias + n0 + 4);
    const float bb[8] = {bv0.x, bv0.y, bv0.z, bv0.w, bv1.x, bv1.y, bv1.z, bv1.w};

#pragma unroll
    for (int i = 0; i < 8; i++) {
        size_t off = (size_t)(m0 + i) * N + n0;
        float v[8];
#pragma unroll
        for (int j = 0; j < 8; j++) v[j] = acc[i][j] + bb[j];
        if (mode == 1) {
#pragma unroll
            for (int j = 0; j < 8; j++) v[j] = fmaxf(v[j], 0.f);
        } else if (mode == 2) {
            float4 r0 = *(const float4*)(res + off);
            float4 r1 = *(const float4*)(res + off + 4);
            v[0] += r0.x; v[1] += r0.y; v[2] += r0.z; v[3] += r0.w;
            v[4] += r1.x; v[5] += r1.y; v[6] += r1.z; v[7] += r1.w;
        }
        *(float4*)(C + off)     = make_float4(v[0], v[1], v[2], v[3]);
        *(float4*)(C + off + 4) = make_float4(v[4], v[5], v[6], v[7]);
    }
}

// ===========================================================================
// Flash attention (fp32, online softmax). One block per (b, h, 64-query tile).
// Q/K/V/out are [B*S, 1024] with head slice at column h*64 (row stride 1024).
// 256 threads: thread (row = tid/4, cg = tid%4) owns 1 query row x 16 cols/dims.
// FLD=68 -> row stride 272 bytes, multiple of 16: float4-safe.
// ===========================================================================
#define FT  64
#define FLD 68
#define FSMEM_BYTES (4 * FT * FLD * sizeof(float))   // Qs,Ks,Vs,Ps

__global__ __launch_bounds__(256, 2)
void flash_kernel(const float* __restrict__ Q,
                  const float* __restrict__ K,
                  const float* __restrict__ V,
                  float* __restrict__ O,
                  int causal)
{
    extern __shared__ float fsmem[];
    float* Qs = fsmem;
    float* Ks = Qs + FT * FLD;
    float* Vs = Ks + FT * FLD;
    float* Ps = Vs + FT * FLD;

    const int tid = threadIdx.x;
    const int row = tid >> 2;   // 0..63
    const int cg  = tid & 3;    // 0..3

    const int bh = blockIdx.y;
    const int b  = bh >> 4;
    const int h  = bh & 15;
    const int q0 = blockIdx.x * FT;

    const size_t base = (size_t)b * SEQ * DM + (size_t)h * DH;
    const float* Qp = Q + base;
    const float* Kp = K + base;
    const float* Vp = V + base;
    float*       Op = O + base;

    // load Q tile, pre-scaled by 1/sqrt(64)
#pragma unroll
    for (int t = 0; t < 4; t++) {
        int v = tid + t * 256;
        int r = v >> 4;
        int c = (v & 15) << 2;
        float4 q4 = *(const float4*)(Qp + (size_t)(q0 + r) * DM + c);
        q4.x *= 0.125f; q4.y *= 0.125f; q4.z *= 0.125f; q4.w *= 0.125f;
        *(float4*)&Qs[r * FLD + c] = q4;
    }

    float o[16];
#pragma unroll
    for (int i = 0; i < 16; i++) o[i] = 0.f;
    float m = -1e30f, l = 0.f;

    const int ntiles = causal ? (q0 / FT + 1) : (SEQ / FT);
    for (int kt = 0; kt < ntiles; kt++) {
        // load K and V tiles
#pragma unroll
        for (int t = 0; t < 4; t++) {
            int v = tid + t * 256;
            int r = v >> 4;
            int c = (v & 15) << 2;
            *(float4*)&Ks[r * FLD + c] =
                *(const float4*)(Kp + (size_t)(kt * FT + r) * DM + c);
            *(float4*)&Vs[r * FLD + c] =
                *(const float4*)(Vp + (size_t)(kt * FT + r) * DM + c);
        }
        __syncthreads();

        // scores for 16 columns
        float s[16];
        const float* qr = &Qs[row * FLD];
#pragma unroll
        for (int c = 0; c < 16; c++) {
            const float* kr = &Ks[(cg * 16 + c) * FLD];
            float acc = 0.f;
#pragma unroll
            for (int d = 0; d < DH; d += 4) {
                float4 qa = *(const float4*)(qr + d);
                float4 kb = *(const float4*)(kr + d);
                acc += qa.x * kb.x + qa.y * kb.y + qa.z * kb.z + qa.w * kb.w;
            }
            s[c] = acc;
        }
        if (causal && kt == ntiles - 1) {
            int qpos = q0 + row;
#pragma unroll
            for (int c = 0; c < 16; c++)
                if (kt * FT + cg * 16 + c > qpos) s[c] = -1e9f;
        }

        // online softmax (4 threads per row: shfl over lane bits 0,1)
        float tm = s[0];
#pragma unroll
        for (int c = 1; c < 16; c++) tm = fmaxf(tm, s[c]);
        tm = fmaxf(tm, __shfl_xor_sync(0xffffffff, tm, 1));
        tm = fmaxf(tm, __shfl_xor_sync(0xffffffff, tm, 2));
        float newm = fmaxf(m, tm);
        float corr = expf(m - newm);
        float psum = 0.f;
#pragma unroll
        for (int c = 0; c < 16; c++) {
            float p = expf(s[c] - newm);
            Ps[row * FLD + cg * 16 + c] = p;
            psum += p;
        }
        psum += __shfl_xor_sync(0xffffffff, psum, 1);
        psum += __shfl_xor_sync(0xffffffff, psum, 2);
        l = l * corr + psum;
        m = newm;
#pragma unroll
        for (int i = 0; i < 16; i++) o[i] *= corr;
        __syncthreads();

        // O += P @ V
        for (int j = 0; j < FT; j++) {
            float p = Ps[row * FLD + j];
            const float* vr = &Vs[j * FLD + cg * 16];
#pragma unroll
            for (int i = 0; i < 16; i++) o[i] += p * vr[i];
        }
        __syncthreads();
    }

    const float rl = 1.f / l;
    float* orow = Op + (size_t)(q0 + row) * DM + cg * 16;
#pragma unroll
    for (int i = 0; i < 16; i += 4)
        *(float4*)(orow + i) =
            make_float4(o[i] * rl, o[i+1] * rl, o[i+2] * rl, o[i+3] * rl);
}

// ===========================================================================
// LayerNorm over last dim (1024). One block (256 thr, float4 each) per row.
// ===========================================================================
__global__ __launch_bounds__(256)
void ln_kernel(const float* __restrict__ X,
               const float* __restrict__ gam,
               const float* __restrict__ bet,
               float* __restrict__ Y)
{
    __shared__ float red[256];
    const int row = blockIdx.x;
    const int tid = threadIdx.x;

    float4 v = ((const float4*)(X + (size_t)row * DM))[tid];

    float s = v.x + v.y + v.z + v.w;
    red[tid] = s;
    __syncthreads();
    for (int off = 128; off > 0; off >>= 1) {
        if (tid < off) red[tid] += red[tid + off];
        __syncthreads();
    }
    const float mu = red[0] * (1.f / DM);
    __syncthreads();

    float dx = v.x - mu, dy = v.y - mu, dz = v.z - mu, dw = v.w - mu;
    red[tid] = dx * dx + dy * dy + dz * dz + dw * dw;
    __syncthreads();
    for (int off = 128; off > 0; off >>= 1) {
        if (tid < off) red[tid] += red[tid + off];
        __syncthreads();
    }
    const float rstd = rsqrtf(red[0] * (1.f / DM) + LN_EPS);

    float4 g4 = ((const float4*)gam)[tid];
    float4 b4 = ((const float4*)bet)[tid];
    float4 y;
    y.x = dx * rstd * g4.x + b4.x;
    y.y = dy * rstd * g4.y + b4.y;
    y.z = dz * rstd * g4.z + b4.z;
    y.w = dw * rstd * g4.w + b4.w;
    ((float4*)(Y + (size_t)row * DM))[tid] = y;
}

// ===========================================================================
// Host orchestration
// ===========================================================================
extern "C" void kernel_launch(void* const* d_in, const int* in_sizes, int n_in,
                              void* d_out, int out_size)
{
    const float* x     = (const float*)d_in[0];
    const float* enc   = (const float*)d_in[1];
    // d_in[2] = mask1 (tril causal), d_in[3] = mask2 (all ones) — structural, unused
    const float* wq1 = (const float*)d_in[4],  *bq1 = (const float*)d_in[5];
    const float* wk1 = (const float*)d_in[6],  *bk1 = (const float*)d_in[7];
    const float* wv1 = (const float*)d_in[8],  *bv1 = (const float*)d_in[9];
    const float* wo1 = (const float*)d_in[10], *bo1 = (const float*)d_in[11];
    const float* wq2 = (const float*)d_in[12], *bq2 = (const float*)d_in[13];
    const float* wk2 = (const float*)d_in[14], *bk2 = (const float*)d_in[15];
    const float* wv2 = (const float*)d_in[16], *bv2 = (const float*)d_in[17];
    const float* wo2 = (const float*)d_in[18], *bo2 = (const float*)d_in[19];
    const float* wf1 = (const float*)d_in[20], *bf1 = (const float*)d_in[21];
    const float* wf2 = (const float*)d_in[22], *bf2 = (const float*)d_in[23];
    const float* g1  = (const float*)d_in[24], *be1 = (const float*)d_in[25];
    const float* g2  = (const float*)d_in[26], *be2 = (const float*)d_in[27];
    const float* g3  = (const float*)d_in[28], *be3 = (const float*)d_in[29];
    float* out = (float*)d_out;

    float *q, *k, *v, *a, *t, *x1, *x2, *ff;
    cudaGetSymbolAddress((void**)&q,  g_q);
    cudaGetSymbolAddress((void**)&k,  g_k);
    cudaGetSymbolAddress((void**)&v,  g_v);
    cudaGetSymbolAddress((void**)&a,  g_a);
    cudaGetSymbolAddress((void**)&t,  g_t);
    cudaGetSymbolAddress((void**)&x1, g_x1);
    cudaGetSymbolAddress((void**)&x2, g_x2);
    cudaGetSymbolAddress((void**)&ff, g_ff);

    cudaFuncSetAttribute(flash_kernel,
                         cudaFuncAttributeMaxDynamicSharedMemorySize,
                         (int)FSMEM_BYTES);

    const dim3 gproj(DM / BN,  MROWS / BM);   // (8, 32)
    const dim3 gff1 (DFF / BN, MROWS / BM);   // (32, 32)
    const dim3 gfl  (SEQ / FT, BATCH * NH);   // (32, 32)

    // ---- self-attention block ----
    sgemm_kernel<<<gproj, 256>>>(x, wq1, bq1, nullptr, q, MROWS, DM, DM, 0);
    sgemm_kernel<<<gproj, 256>>>(x, wk1, bk1, nullptr, k, MROWS, DM, DM, 0);
    sgemm_kernel<<<gproj, 256>>>(x, wv1, bv1, nullptr, v, MROWS, DM, DM, 0);
    flash_kernel<<<gfl, 256, FSMEM_BYTES>>>(q, k, v, a, 1);
    sgemm_kernel<<<gproj, 256>>>(a, wo1, bo1, x, t, MROWS, DM, DM, 2);
    ln_kernel<<<MROWS, 256>>>(t, g1, be1, x1);

    // ---- cross-attention block ----
    sgemm_kernel<<<gproj, 256>>>(x1,  wq2, bq2, nullptr, q, MROWS, DM, DM, 0);
    sgemm_kernel<<<gproj, 256>>>(enc, wk2, bk2, nullptr, k, MROWS, DM, DM, 0);
    sgemm_kernel<<<gproj, 256>>>(enc, wv2, bv2, nullptr, v, MROWS, DM, DM, 0);
    flash_kernel<<<gfl, 256, FSMEM_BYTES>>>(q, k, v, a, 0);
    sgemm_kernel<<<gproj, 256>>>(a, wo2, bo2, x1, t, MROWS, DM, DM, 2);
    ln_kernel<<<MROWS, 256>>>(t, g2, be2, x2);

    // ---- FFN block ----
    sgemm_kernel<<<gff1,  256>>>(x2, wf1, bf1, nullptr, ff, MROWS, DFF, DM, 1);
    sgemm_kernel<<<gproj, 256>>>(ff, wf2, bf2, x2, t, MROWS, DM, DFF, 2);
    ln_kernel<<<MROWS, 256>>>(t, g3, be3, out);
}

// round 5
// speedup vs baseline: 1.0438x; 1.0438x over previous
#include <cuda_runtime.h>
#include <cuda_bf16.h>
#include <math.h>
#include <stdint.h>

// ---------------------------------------------------------------------------
// DecoderLayer: x -> self-attn(causal)+res+LN -> cross-attn+res+LN -> FFN+res+LN
// B=2, S=2048, d_model=1024, H=16, d_head=64, d_ff=4096.
// GEMMs: mma.sync.m16n8k16 bf16 (bf16x3 split -> fp32-class accuracy).
// (tcgen05 unavailable: harness compiles for plain sm_100, no 'a' suffix.)
// ---------------------------------------------------------------------------

#define DM     1024
#define DFF    4096
#define BATCH  2
#define SEQ    2048
#define NH     16
#define DH     64
#define MROWS  (BATCH * SEQ)   // 4096
#define LN_EPS 1e-5f

// ---- fp32 scratch ----
__device__ float g_q [MROWS * DM];
__device__ float g_k [MROWS * DM];
__device__ float g_v [MROWS * DM];
__device__ float g_a [MROWS * DM];
__device__ float g_t [MROWS * DM];
__device__ float g_x1[MROWS * DM];
__device__ float g_x2[MROWS * DM];
__device__ float g_ff[(size_t)MROWS * DFF];

// ---- bf16 hi/lo pools (element offsets) ----
#define MB (1024 * 1024)
#define OFF_WQ1  (0 * MB)
#define OFF_WK1  (1 * MB)
#define OFF_WV1  (2 * MB)
#define OFF_WO1  (3 * MB)
#define OFF_WQ2  (4 * MB)
#define OFF_WK2  (5 * MB)
#define OFF_WV2  (6 * MB)
#define OFF_WO2  (7 * MB)
#define OFF_WF1  (8 * MB)     // 4M
#define OFF_WF2  (12 * MB)    // 4M
#define OFF_X    (16 * MB)    // 4M
#define OFF_ENC  (20 * MB)    // 4M
#define OFF_A    (24 * MB)    // 4M
#define OFF_X1   (28 * MB)    // 4M
#define OFF_X2   (32 * MB)    // 4M
#define OFF_FF   (36 * MB)    // 16M
#define POOL_ELEMS ((size_t)52 * MB)

__device__ __nv_bfloat16 g_hi[POOL_ELEMS];
__device__ __nv_bfloat16 g_lo[POOL_ELEMS];

// ===========================================================================
// PTX helpers (sm_80-compatible only)
// ===========================================================================
__device__ __forceinline__ uint32_t smem_u32(const void* p) {
    uint32_t a;
    asm("{ .reg .u64 t; cvta.to.shared.u64 t, %1; cvt.u32.u64 %0, t; }"
        : "=r"(a) : "l"(p));
    return a;
}
#define CP_ASYNC16(dst, src) \
    asm volatile("cp.async.cg.shared.global [%0], [%1], 16;" :: "r"(dst), "l"(src))
#define CP_COMMIT() asm volatile("cp.async.commit_group;" ::: "memory")
#define CP_WAIT1()  asm volatile("cp.async.wait_group 1;" ::: "memory")
#define CP_WAIT0()  asm volatile("cp.async.wait_group 0;" ::: "memory")

__device__ __forceinline__ void ldsm4(uint32_t* r, uint32_t addr) {
    asm volatile("ldmatrix.sync.aligned.m8n8.x4.shared.b16 {%0,%1,%2,%3}, [%4];"
        : "=r"(r[0]), "=r"(r[1]), "=r"(r[2]), "=r"(r[3]) : "r"(addr));
}
__device__ __forceinline__ void mma_bf16(float* d, const uint32_t* a, const uint32_t* b) {
    asm volatile(
        "mma.sync.aligned.m16n8k16.row.col.f32.bf16.bf16.f32 "
        "{%0,%1,%2,%3}, {%4,%5,%6,%7}, {%8,%9}, {%0,%1,%2,%3};"
        : "+f"(d[0]), "+f"(d[1]), "+f"(d[2]), "+f"(d[3])
        : "r"(a[0]), "r"(a[1]), "r"(a[2]), "r"(a[3]), "r"(b[0]), "r"(b[1]));
}

__device__ __forceinline__ void split_bf16(float x, __nv_bfloat16& h, __nv_bfloat16& l) {
    h = __float2bfloat16(x);
    l = __float2bfloat16(x - __bfloat162float(h));
}

// ===========================================================================
// HMMA GEMM: C[M,N] = A[M,K] @ W[N,K]^T + bias + (relu | res)
// bf16x3: D = Ahi*Whi + Ahi*Wlo + Alo*Whi (fp32 accum in registers).
// 128x128x32 tile, 256 thr, warp grid 4(M)x2(N), warp tile 32x64.
// Smem rows padded to 40 elems (80B): ldmatrix conflict-free.
// ===========================================================================
#define ASTR 40
#define STAGE_ELEMS (128 * ASTR)

__global__ __launch_bounds__(256, 1)
void tc_gemm(const __nv_bfloat16* __restrict__ Ahi, const __nv_bfloat16* __restrict__ Alo,
             const __nv_bfloat16* __restrict__ Whi, const __nv_bfloat16* __restrict__ Wlo,
             const float* __restrict__ bias, const float* __restrict__ res,
             float* __restrict__ C,
             __nv_bfloat16* __restrict__ Chi, __nv_bfloat16* __restrict__ Clo,
             int M, int N, int K, int mode)
{
    __shared__ __nv_bfloat16 sA[2][STAGE_ELEMS];
    __shared__ __nv_bfloat16 sB[2][STAGE_ELEMS];

    const int tid    = threadIdx.x;
    const int wid    = tid >> 5;
    const int lane   = tid & 31;
    const int warp_m = wid >> 1;     // 0..3
    const int warp_n = wid & 1;      // 0..1
    const int m0     = blockIdx.y * 128;
    const int n0     = blockIdx.x * 128;

    // cp.async fill mapping: row = tid/2, two 8-elem chunks per thread
    const int frow = tid >> 1;
    const int fcol = (tid & 1) * 16;   // elems (covers 16 of 32; two chunks of 8)

    const uint32_t sa0 = smem_u32(&sA[0][0]);
    const uint32_t sb0 = smem_u32(&sB[0][0]);

    float d[2][8][4];
#pragma unroll
    for (int mi = 0; mi < 2; mi++)
#pragma unroll
        for (int nj = 0; nj < 8; nj++)
#pragma unroll
            for (int e = 0; e < 4; e++) d[mi][nj][e] = 0.f;

    const int nS    = K >> 5;      // 32-elem K steps per pass
    const int total = nS * 3;

    // ---- stage issue helper (macro-ish via lambda) ----
    auto issue = [&](int i, int buf) {
        const int pass = i / nS;
        const int k0   = (i - pass * nS) << 5;
        const __nv_bfloat16* Ap = (pass == 2) ? Alo : Ahi;
        const __nv_bfloat16* Wp = (pass == 1) ? Wlo : Whi;
        const __nv_bfloat16* ga = Ap + (size_t)(m0 + frow) * K + k0 + fcol;
        const __nv_bfloat16* gb = Wp + (size_t)(n0 + frow) * K + k0 + fcol;
        uint32_t da = sa0 + (uint32_t)(buf * STAGE_ELEMS + frow * ASTR + fcol) * 2;
        uint32_t db = sb0 + (uint32_t)(buf * STAGE_ELEMS + frow * ASTR + fcol) * 2;
        CP_ASYNC16(da,      ga);
        CP_ASYNC16(da + 16, ga + 8);
        CP_ASYNC16(db,      gb);
        CP_ASYNC16(db + 16, gb + 8);
    };

    issue(0, 0); CP_COMMIT();

    for (int i = 0; i < total; i++) {
        const int buf = i & 1;
        if (i + 1 < total) { issue(i + 1, buf ^ 1); CP_COMMIT(); CP_WAIT1(); }
        else               { CP_WAIT0(); }
        __syncthreads();

        const uint32_t sa = sa0 + (uint32_t)(buf * STAGE_ELEMS) * 2;
        const uint32_t sb = sb0 + (uint32_t)(buf * STAGE_ELEMS) * 2;

#pragma unroll
        for (int ks = 0; ks < 2; ks++) {
            uint32_t afr[2][4];
#pragma unroll
            for (int mi = 0; mi < 2; mi++) {
                int row = warp_m * 32 + mi * 16 + (lane & 15);
                int col = ks * 16 + ((lane >> 4) & 1) * 8;
                ldsm4(afr[mi], sa + (uint32_t)(row * ASTR + col) * 2);
            }
            uint32_t bfr[8][2];
#pragma unroll
            for (int jj = 0; jj < 4; jj++) {
                int row = warp_n * 64 + jj * 16 + (lane & 7) + ((lane >> 4) & 1) * 8;
                int col = ks * 16 + ((lane >> 3) & 1) * 8;
                uint32_t t[4];
                ldsm4(t, sb + (uint32_t)(row * ASTR + col) * 2);
                bfr[jj*2][0]   = t[0]; bfr[jj*2][1]   = t[1];
                bfr[jj*2+1][0] = t[2]; bfr[jj*2+1][1] = t[3];
            }
#pragma unroll
            for (int mi = 0; mi < 2; mi++)
#pragma unroll
                for (int nj = 0; nj < 8; nj++)
                    mma_bf16(d[mi][nj], afr[mi], bfr[nj]);
        }
        __syncthreads();
    }

    // ---- epilogue ----
    const int lr = lane >> 2;          // 0..7
    const int lc = (lane & 3) * 2;     // 0,2,4,6

#pragma unroll
    for (int mi = 0; mi < 2; mi++) {
        const int r0 = m0 + warp_m * 32 + mi * 16 + lr;
#pragma unroll
        for (int nj = 0; nj < 8; nj++) {
            const int c = n0 + warp_n * 64 + nj * 8 + lc;
            const float b0 = bias[c], b1 = bias[c + 1];
#pragma unroll
            for (int half = 0; half < 2; half++) {
                const int rr = r0 + half * 8;
                float v0 = d[mi][nj][half * 2 + 0] + b0;
                float v1 = d[mi][nj][half * 2 + 1] + b1;
                if (mode == 1) {
                    v0 = fmaxf(v0, 0.f); v1 = fmaxf(v1, 0.f);
                } else if (mode == 2) {
                    const float2 rv = *(const float2*)(res + (size_t)rr * N + c);
                    v0 += rv.x; v1 += rv.y;
                }
                *(float2*)(C + (size_t)rr * N + c) = make_float2(v0, v1);
                if (Chi) {
                    __nv_bfloat16 h0, l0, h1, l1;
                    split_bf16(v0, h0, l0);
                    split_bf16(v1, h1, l1);
                    *(__nv_bfloat162*)(Chi + (size_t)rr * N + c) = __nv_bfloat162(h0, h1);
                    *(__nv_bfloat162*)(Clo + (size_t)rr * N + c) = __nv_bfloat162(l0, l1);
                }
            }
        }
    }
}

// ===========================================================================
// fp32 -> (bf16 hi, bf16 lo) split converter
// ===========================================================================
__global__ __launch_bounds__(256)
void cvt_kernel(const float* __restrict__ X,
                __nv_bfloat16* __restrict__ hi, __nv_bfloat16* __restrict__ lo,
                int n)
{
    int i = (blockIdx.x * 256 + threadIdx.x) * 4;
    if (i >= n) return;
    float4 v = *(const float4*)(X + i);
    __nv_bfloat16 h0, l0, h1, l1, h2, l2, h3, l3;
    split_bf16(v.x, h0, l0); split_bf16(v.y, h1, l1);
    split_bf16(v.z, h2, l2); split_bf16(v.w, h3, l3);
    ((__nv_bfloat162*)(hi + i))[0] = __nv_bfloat162(h0, h1);
    ((__nv_bfloat162*)(hi + i))[1] = __nv_bfloat162(h2, h3);
    ((__nv_bfloat162*)(lo + i))[0] = __nv_bfloat162(l0, l1);
    ((__nv_bfloat162*)(lo + i))[1] = __nv_bfloat162(l2, l3);
}

// ===========================================================================
// Flash attention (fp32, online softmax) — also emits hi/lo bf16 split.
// ===========================================================================
#define FT  64
#define FLD 68
#define FSMEM_BYTES (4 * FT * FLD * sizeof(float))

__global__ __launch_bounds__(256, 2)
void flash_kernel(const float* __restrict__ Q,
                  const float* __restrict__ K,
                  const float* __restrict__ V,
                  float* __restrict__ O,
                  __nv_bfloat16* __restrict__ Ohi,
                  __nv_bfloat16* __restrict__ Olo,
                  int causal)
{
    extern __shared__ float fsmem[];
    float* Qs = fsmem;
    float* Ks = Qs + FT * FLD;
    float* Vs = Ks + FT * FLD;
    float* Ps = Vs + FT * FLD;

    const int tid = threadIdx.x;
    const int row = tid >> 2;
    const int cg  = tid & 3;

    const int bh = blockIdx.y;
    const int b  = bh >> 4;
    const int h  = bh & 15;
    const int q0 = blockIdx.x * FT;

    const size_t base = (size_t)b * SEQ * DM + (size_t)h * DH;
    const float* Qp = Q + base;
    const float* Kp = K + base;
    const float* Vp = V + base;

#pragma unroll
    for (int t = 0; t < 4; t++) {
        int v = tid + t * 256;
        int r = v >> 4;
        int c = (v & 15) << 2;
        float4 q4 = *(const float4*)(Qp + (size_t)(q0 + r) * DM + c);
        q4.x *= 0.125f; q4.y *= 0.125f; q4.z *= 0.125f; q4.w *= 0.125f;
        *(float4*)&Qs[r * FLD + c] = q4;
    }

    float o[16];
#pragma unroll
    for (int i = 0; i < 16; i++) o[i] = 0.f;
    float m = -1e30f, l = 0.f;

    const int ntiles = causal ? (q0 / FT + 1) : (SEQ / FT);
    for (int kt = 0; kt < ntiles; kt++) {
#pragma unroll
        for (int t = 0; t < 4; t++) {
            int v = tid + t * 256;
            int r = v >> 4;
            int c = (v & 15) << 2;
            *(float4*)&Ks[r * FLD + c] =
                *(const float4*)(Kp + (size_t)(kt * FT + r) * DM + c);
            *(float4*)&Vs[r * FLD + c] =
                *(const float4*)(Vp + (size_t)(kt * FT + r) * DM + c);
        }
        __syncthreads();

        float s[16];
        const float* qr = &Qs[row * FLD];
#pragma unroll
        for (int c = 0; c < 16; c++) {
            const float* kr = &Ks[(cg * 16 + c) * FLD];
            float acc = 0.f;
#pragma unroll
            for (int d = 0; d < DH; d += 4) {
                float4 qa = *(const float4*)(qr + d);
                float4 kb = *(const float4*)(kr + d);
                acc += qa.x * kb.x + qa.y * kb.y + qa.z * kb.z + qa.w * kb.w;
            }
            s[c] = acc;
        }
        if (causal && kt == ntiles - 1) {
            int qpos = q0 + row;
#pragma unroll
            for (int c = 0; c < 16; c++)
                if (kt * FT + cg * 16 + c > qpos) s[c] = -1e9f;
        }

        float tm = s[0];
#pragma unroll
        for (int c = 1; c < 16; c++) tm = fmaxf(tm, s[c]);
        tm = fmaxf(tm, __shfl_xor_sync(0xffffffff, tm, 1));
        tm = fmaxf(tm, __shfl_xor_sync(0xffffffff, tm, 2));
        float newm = fmaxf(m, tm);
        float corr = expf(m - newm);
        float psum = 0.f;
#pragma unroll
        for (int c = 0; c < 16; c++) {
            float p = expf(s[c] - newm);
            Ps[row * FLD + cg * 16 + c] = p;
            psum += p;
        }
        psum += __shfl_xor_sync(0xffffffff, psum, 1);
        psum += __shfl_xor_sync(0xffffffff, psum, 2);
        l = l * corr + psum;
        m = newm;
#pragma unroll
        for (int i = 0; i < 16; i++) o[i] *= corr;
        __syncthreads();

        for (int j = 0; j < FT; j++) {
            float p = Ps[row * FLD + j];
            const float4* vr = (const float4*)&Vs[j * FLD + cg * 16];
            float4 v0 = vr[0], v1 = vr[1], v2 = vr[2], v3 = vr[3];
            o[0]  += p * v0.x; o[1]  += p * v0.y; o[2]  += p * v0.z; o[3]  += p * v0.w;
            o[4]  += p * v1.x; o[5]  += p * v1.y; o[6]  += p * v1.z; o[7]  += p * v1.w;
            o[8]  += p * v2.x; o[9]  += p * v2.y; o[10] += p * v2.z; o[11] += p * v2.w;
            o[12] += p * v3.x; o[13] += p * v3.y; o[14] += p * v3.z; o[15] += p * v3.w;
        }
        __syncthreads();
    }

    const float rl = 1.f / l;
    const size_t ooff = base + (size_t)(q0 + row) * DM + cg * 16;
    float* orow = O + ooff;
#pragma unroll
    for (int i = 0; i < 16; i++) o[i] *= rl;
#pragma unroll
    for (int i = 0; i < 16; i += 4)
        *(float4*)(orow + i) = make_float4(o[i], o[i+1], o[i+2], o[i+3]);
#pragma unroll
    for (int jp = 0; jp < 8; jp++) {
        __nv_bfloat16 h0, l0, h1, l1;
        split_bf16(o[jp*2],   h0, l0);
        split_bf16(o[jp*2+1], h1, l1);
        ((__nv_bfloat162*)(Ohi + ooff))[jp] = __nv_bfloat162(h0, h1);
        ((__nv_bfloat162*)(Olo + ooff))[jp] = __nv_bfloat162(l0, l1);
    }
}

// ===========================================================================
// LayerNorm (1024), optional bf16 hi/lo split output
// ===========================================================================
__global__ __launch_bounds__(256)
void ln_kernel(const float* __restrict__ X,
               const float* __restrict__ gam,
               const float* __restrict__ bet,
               float* __restrict__ Y,
               __nv_bfloat16* __restrict__ Yhi,
               __nv_bfloat16* __restrict__ Ylo)
{
    __shared__ float red[256];
    const int row = blockIdx.x;
    const int tid = threadIdx.x;

    float4 v = ((const float4*)(X + (size_t)row * DM))[tid];

    float s = v.x + v.y + v.z + v.w;
    red[tid] = s;
    __syncthreads();
    for (int off = 128; off > 0; off >>= 1) {
        if (tid < off) red[tid] += red[tid + off];
        __syncthreads();
    }
    const float mu = red[0] * (1.f / DM);
    __syncthreads();

    float dx = v.x - mu, dy = v.y - mu, dz = v.z - mu, dw = v.w - mu;
    red[tid] = dx * dx + dy * dy + dz * dz + dw * dw;
    __syncthreads();
    for (int off = 128; off > 0; off >>= 1) {
        if (tid < off) red[tid] += red[tid + off];
        __syncthreads();
    }
    const float rstd = rsqrtf(red[0] * (1.f / DM) + LN_EPS);

    float4 g4 = ((const float4*)gam)[tid];
    float4 b4 = ((const float4*)bet)[tid];
    float4 y;
    y.x = dx * rstd * g4.x + b4.x;
    y.y = dy * rstd * g4.y + b4.y;
    y.z = dz * rstd * g4.z + b4.z;
    y.w = dw * rstd * g4.w + b4.w;
    ((float4*)(Y + (size_t)row * DM))[tid] = y;

    if (Yhi) {
        size_t off = (size_t)row * DM + tid * 4;
        __nv_bfloat16 h0, l0, h1, l1, h2, l2, h3, l3;
        split_bf16(y.x, h0, l0); split_bf16(y.y, h1, l1);
        split_bf16(y.z, h2, l2); split_bf16(y.w, h3, l3);
        ((__nv_bfloat162*)(Yhi + off))[0] = __nv_bfloat162(h0, h1);
        ((__nv_bfloat162*)(Yhi + off))[1] = __nv_bfloat162(h2, h3);
        ((__nv_bfloat162*)(Ylo + off))[0] = __nv_bfloat162(l0, l1);
        ((__nv_bfloat162*)(Ylo + off))[1] = __nv_bfloat162(l2, l3);
    }
}

// ===========================================================================
// Host orchestration
// ===========================================================================
static inline void cvt(const float* src, __nv_bfloat16* hi, __nv_bfloat16* lo,
                       size_t off, int n) {
    cvt_kernel<<<(n / 4 + 255) / 256, 256>>>(src, hi + off, lo + off, n);
}

extern "C" void kernel_launch(void* const* d_in, const int* in_sizes, int n_in,
                              void* d_out, int out_size)
{
    const float* x     = (const float*)d_in[0];
    const float* enc   = (const float*)d_in[1];
    // d_in[2] mask1 (tril), d_in[3] mask2 (ones) — structural, unused
    const float* wq1 = (const float*)d_in[4],  *bq1 = (const float*)d_in[5];
    const float* wk1 = (const float*)d_in[6],  *bk1 = (const float*)d_in[7];
    const float* wv1 = (const float*)d_in[8],  *bv1 = (const float*)d_in[9];
    const float* wo1 = (const float*)d_in[10], *bo1 = (const float*)d_in[11];
    const float* wq2 = (const float*)d_in[12], *bq2 = (const float*)d_in[13];
    const float* wk2 = (const float*)d_in[14], *bk2 = (const float*)d_in[15];
    const float* wv2 = (const float*)d_in[16], *bv2 = (const float*)d_in[17];
    const float* wo2 = (const float*)d_in[18], *bo2 = (const float*)d_in[19];
    const float* wf1 = (const float*)d_in[20], *bf1 = (const float*)d_in[21];
    const float* wf2 = (const float*)d_in[22], *bf2 = (const float*)d_in[23];
    const float* g1  = (const float*)d_in[24], *be1 = (const float*)d_in[25];
    const float* g2  = (const float*)d_in[26], *be2 = (const float*)d_in[27];
    const float* g3  = (const float*)d_in[28], *be3 = (const float*)d_in[29];
    float* out = (float*)d_out;

    float *q, *k, *v, *a, *t, *x1, *x2, *ff;
    __nv_bfloat16 *hi, *lo;
    cudaGetSymbolAddress((void**)&q,  g_q);
    cudaGetSymbolAddress((void**)&k,  g_k);
    cudaGetSymbolAddress((void**)&v,  g_v);
    cudaGetSymbolAddress((void**)&a,  g_a);
    cudaGetSymbolAddress((void**)&t,  g_t);
    cudaGetSymbolAddress((void**)&x1, g_x1);
    cudaGetSymbolAddress((void**)&x2, g_x2);
    cudaGetSymbolAddress((void**)&ff, g_ff);
    cudaGetSymbolAddress((void**)&hi, g_hi);
    cudaGetSymbolAddress((void**)&lo, g_lo);

    cudaFuncSetAttribute(flash_kernel,
                         cudaFuncAttributeMaxDynamicSharedMemorySize, (int)FSMEM_BYTES);

    // ---- converts ----
    cvt(wq1, hi, lo, OFF_WQ1, DM * DM);
    cvt(wk1, hi, lo, OFF_WK1, DM * DM);
    cvt(wv1, hi, lo, OFF_WV1, DM * DM);
    cvt(wo1, hi, lo, OFF_WO1, DM * DM);
    cvt(wq2, hi, lo, OFF_WQ2, DM * DM);
    cvt(wk2, hi, lo, OFF_WK2, DM * DM);
    cvt(wv2, hi, lo, OFF_WV2, DM * DM);
    cvt(wo2, hi, lo, OFF_WO2, DM * DM);
    cvt(wf1, hi, lo, OFF_WF1, DFF * DM);
    cvt(wf2, hi, lo, OFF_WF2, DM * DFF);
    cvt(x,   hi, lo, OFF_X,   MROWS * DM);
    cvt(enc, hi, lo, OFF_ENC, MROWS * DM);

    const dim3 gproj(DM / 128,  MROWS / 128);   // (8, 32)
    const dim3 gff1 (DFF / 128, MROWS / 128);   // (32, 32)
    const dim3 gfl  (SEQ / FT, BATCH * NH);

    // ---- self-attention ----
    tc_gemm<<<gproj, 256>>>(hi+OFF_X, lo+OFF_X, hi+OFF_WQ1, lo+OFF_WQ1,
                            bq1, nullptr, q, nullptr, nullptr, MROWS, DM, DM, 0);
    tc_gemm<<<gproj, 256>>>(hi+OFF_X, lo+OFF_X, hi+OFF_WK1, lo+OFF_WK1,
                            bk1, nullptr, k, nullptr, nullptr, MROWS, DM, DM, 0);
    tc_gemm<<<gproj, 256>>>(hi+OFF_X, lo+OFF_X, hi+OFF_WV1, lo+OFF_WV1,
                            bv1, nullptr, v, nullptr, nullptr, MROWS, DM, DM, 0);
    flash_kernel<<<gfl, 256, FSMEM_BYTES>>>(q, k, v, a, hi+OFF_A, lo+OFF_A, 1);
    tc_gemm<<<gproj, 256>>>(hi+OFF_A, lo+OFF_A, hi+OFF_WO1, lo+OFF_WO1,
                            bo1, x, t, nullptr, nullptr, MROWS, DM, DM, 2);
    ln_kernel<<<MROWS, 256>>>(t, g1, be1, x1, hi+OFF_X1, lo+OFF_X1);

    // ---- cross-attention ----
    tc_gemm<<<gproj, 256>>>(hi+OFF_X1, lo+OFF_X1, hi+OFF_WQ2, lo+OFF_WQ2,
                            bq2, nullptr, q, nullptr, nullptr, MROWS, DM, DM, 0);
    tc_gemm<<<gproj, 256>>>(hi+OFF_ENC, lo+OFF_ENC, hi+OFF_WK2, lo+OFF_WK2,
                            bk2, nullptr, k, nullptr, nullptr, MROWS, DM, DM, 0);
    tc_gemm<<<gproj, 256>>>(hi+OFF_ENC, lo+OFF_ENC, hi+OFF_WV2, lo+OFF_WV2,
                            bv2, nullptr, v, nullptr, nullptr, MROWS, DM, DM, 0);
    flash_kernel<<<gfl, 256, FSMEM_BYTES>>>(q, k, v, a, hi+OFF_A, lo+OFF_A, 0);
    tc_gemm<<<gproj, 256>>>(hi+OFF_A, lo+OFF_A, hi+OFF_WO2, lo+OFF_WO2,
                            bo2, x1, t, nullptr, nullptr, MROWS, DM, DM, 2);
    ln_kernel<<<MROWS, 256>>>(t, g2, be2, x2, hi+OFF_X2, lo+OFF_X2);

    // ---- FFN ----
    tc_gemm<<<gff1, 256>>>(hi+OFF_X2, lo+OFF_X2, hi+OFF_WF1, lo+OFF_WF1,
                           bf1, nullptr, ff, hi+OFF_FF, lo+OFF_FF,
                           MROWS, DFF, DM, 1);
    tc_gemm<<<gproj, 256>>>(hi+OFF_FF, lo+OFF_FF, hi+OFF_WF2, lo+OFF_WF2,
                            bf2, x2, t, nullptr, nullptr, MROWS, DM, DFF, 2);
    ln_kernel<<<MROWS, 256>>>(t, g3, be3, out, nullptr, nullptr);
}

// round 6
// speedup vs baseline: 1.1445x; 1.0965x over previous
#include <cuda_runtime.h>
#include <cuda_bf16.h>
#include <math.h>
#include <stdint.h>

// ---------------------------------------------------------------------------
// DecoderLayer: x -> self-attn(causal)+res+LN -> cross-attn+res+LN -> FFN+res+LN
// B=2, S=2048, d_model=1024, H=16, d_head=64, d_ff=4096.
// GEMMs: mma.sync.m16n8k16 bf16 (bf16x3) — 3-stage cp.async, 2 CTA/SM.
// ---------------------------------------------------------------------------

#define DM     1024
#define DFF    4096
#define BATCH  2
#define SEQ    2048
#define NH     16
#define DH     64
#define MROWS  (BATCH * SEQ)   // 4096
#define LN_EPS 1e-5f

// ---- fp32 scratch ----
__device__ float g_q [MROWS * DM];
__device__ float g_k [MROWS * DM];
__device__ float g_v [MROWS * DM];
__device__ float g_a [MROWS * DM];
__device__ float g_t [MROWS * DM];
__device__ float g_x1[MROWS * DM];
__device__ float g_x2[MROWS * DM];
__device__ float g_ff[(size_t)MROWS * DFF];

// ---- bf16 hi/lo pools (element offsets); WQ1/WK1/WV1 contiguous => merged QKV,
//      WK2/WV2 contiguous => merged KV ----
#define MB (1024 * 1024)
#define OFF_WQ1  (0 * MB)
#define OFF_WK1  (1 * MB)
#define OFF_WV1  (2 * MB)
#define OFF_WO1  (3 * MB)
#define OFF_WQ2  (4 * MB)
#define OFF_WK2  (5 * MB)
#define OFF_WV2  (6 * MB)
#define OFF_WO2  (7 * MB)
#define OFF_WF1  (8 * MB)     // 4M
#define OFF_WF2  (12 * MB)    // 4M
#define OFF_X    (16 * MB)    // 4M
#define OFF_ENC  (20 * MB)    // 4M
#define OFF_A    (24 * MB)    // 4M
#define OFF_X1   (28 * MB)    // 4M
#define OFF_X2   (32 * MB)    // 4M
#define OFF_FF   (36 * MB)    // 16M
#define POOL_ELEMS ((size_t)52 * MB)

__device__ __nv_bfloat16 g_hi[POOL_ELEMS];
__device__ __nv_bfloat16 g_lo[POOL_ELEMS];

// ===========================================================================
// PTX helpers (sm_80-compatible only; tcgen05 rejected by harness's sm_100)
// ===========================================================================
__device__ __forceinline__ uint32_t smem_u32(const void* p) {
    uint32_t a;
    asm("{ .reg .u64 t; cvta.to.shared.u64 t, %1; cvt.u32.u64 %0, t; }"
        : "=r"(a) : "l"(p));
    return a;
}
#define CP_ASYNC16(dst, src) \
    asm volatile("cp.async.cg.shared.global [%0], [%1], 16;" :: "r"(dst), "l"(src))
#define CP_COMMIT() asm volatile("cp.async.commit_group;" ::: "memory")
#define CP_WAIT1()  asm volatile("cp.async.wait_group 1;" ::: "memory")

__device__ __forceinline__ void ldsm4(uint32_t* r, uint32_t addr) {
    asm volatile("ldmatrix.sync.aligned.m8n8.x4.shared.b16 {%0,%1,%2,%3}, [%4];"
        : "=r"(r[0]), "=r"(r[1]), "=r"(r[2]), "=r"(r[3]) : "r"(addr));
}
__device__ __forceinline__ void mma_bf16(float* d, const uint32_t* a, const uint32_t* b) {
    asm volatile(
        "mma.sync.aligned.m16n8k16.row.col.f32.bf16.bf16.f32 "
        "{%0,%1,%2,%3}, {%4,%5,%6,%7}, {%8,%9}, {%0,%1,%2,%3};"
        : "+f"(d[0]), "+f"(d[1]), "+f"(d[2]), "+f"(d[3])
        : "r"(a[0]), "r"(a[1]), "r"(a[2]), "r"(a[3]), "r"(b[0]), "r"(b[1]));
}

__device__ __forceinline__ void split_bf16(float x, __nv_bfloat16& h, __nv_bfloat16& l) {
    h = __float2bfloat16(x);
    l = __float2bfloat16(x - __bfloat162float(h));
}

// ===========================================================================
// HMMA GEMM with section-split output:
//   C[M, NSEC*ldc] = A[M,K] @ W[NSEC*ldc, K]^T ; col n belongs to section n/ldc,
//   written to Cs[sec][row*ldc + n%ldc] with bias[sec].
// bf16x3: hi*hi + hi*lo + lo*hi accumulated fp32.
// 128x128x32 CTA tile, 256 thr (4Mx2N warps, 32x64/warp), 3-stage cp.async,
// one __syncthreads per K-step, 2 CTAs/SM.
// ===========================================================================
#define NSTAGE 3
#define ASTR   40                      // smem row stride (elems); 80B rows
#define STG_E  (128 * ASTR)            // elems per stage per operand
#define GSMEM  (NSTAGE * 2 * STG_E * 2)  // 61440 bytes

__global__ __launch_bounds__(256, 2)
void tc_gemm(const __nv_bfloat16* __restrict__ Ahi, const __nv_bfloat16* __restrict__ Alo,
             const __nv_bfloat16* __restrict__ Whi, const __nv_bfloat16* __restrict__ Wlo,
             const float* __restrict__ bias0, const float* __restrict__ bias1,
             const float* __restrict__ bias2,
             const float* __restrict__ res,
             float* __restrict__ C0, float* __restrict__ C1, float* __restrict__ C2,
             __nv_bfloat16* __restrict__ Chi, __nv_bfloat16* __restrict__ Clo,
             int K, int ldc, int mode)
{
    extern __shared__ __nv_bfloat16 smem[];
    __nv_bfloat16* sA = smem;                      // [NSTAGE][STG_E]
    __nv_bfloat16* sB = smem + NSTAGE * STG_E;     // [NSTAGE][STG_E]

    const int tid    = threadIdx.x;
    const int wid    = tid >> 5;
    const int lane   = tid & 31;
    const int warp_m = wid >> 1;
    const int warp_n = wid & 1;
    const int m0     = blockIdx.y * 128;
    const int gn0    = blockIdx.x * 128;           // global col in concatenated W

    const int frow = tid >> 1;
    const int fcol = (tid & 1) * 16;

    const uint32_t sa0 = smem_u32(sA);
    const uint32_t sb0 = smem_u32(sB);

    float d[2][8][4];
#pragma unroll
    for (int mi = 0; mi < 2; mi++)
#pragma unroll
        for (int nj = 0; nj < 8; nj++)
#pragma unroll
            for (int e = 0; e < 4; e++) d[mi][nj][e] = 0.f;

    const int nS    = K >> 5;
    const int total = nS * 3;

    auto issue = [&](int i, int buf) {
        const __nv_bfloat16* Ap = (i >= 2 * nS) ? Alo : Ahi;
        const __nv_bfloat16* Wp = (i >= nS && i < 2 * nS) ? Wlo : Whi;
        const int kk = i - ((i >= 2 * nS) ? 2 * nS : (i >= nS ? nS : 0));
        const int k0 = kk << 5;
        const __nv_bfloat16* ga = Ap + (size_t)(m0 + frow) * K + k0 + fcol;
        const __nv_bfloat16* gb = Wp + (size_t)(gn0 + frow) * K + k0 + fcol;
        uint32_t da = sa0 + (uint32_t)(buf * STG_E + frow * ASTR + fcol) * 2;
        uint32_t db = sb0 + (uint32_t)(buf * STG_E + frow * ASTR + fcol) * 2;
        CP_ASYNC16(da,      ga);
        CP_ASYNC16(da + 16, ga + 8);
        CP_ASYNC16(db,      gb);
        CP_ASYNC16(db + 16, gb + 8);
    };

    issue(0, 0); CP_COMMIT();
    issue(1, 1); CP_COMMIT();

    for (int i = 0; i < total; i++) {
        const int buf = i % NSTAGE;
        CP_WAIT1();            // stage i complete (stage i+1 may be in flight)
        __syncthreads();       // all warps done with buffer (i-1)%NSTAGE
        if (i + 2 < total) issue(i + 2, (i + 2) % NSTAGE);
        CP_COMMIT();

        const uint32_t sa = sa0 + (uint32_t)(buf * STG_E) * 2;
        const uint32_t sb = sb0 + (uint32_t)(buf * STG_E) * 2;

#pragma unroll
        for (int ks = 0; ks < 2; ks++) {
            uint32_t afr[2][4];
#pragma unroll
            for (int mi = 0; mi < 2; mi++) {
                int row = warp_m * 32 + mi * 16 + (lane & 15);
                int col = ks * 16 + ((lane >> 4) & 1) * 8;
                ldsm4(afr[mi], sa + (uint32_t)(row * ASTR + col) * 2);
            }
            uint32_t bfr[8][2];
#pragma unroll
            for (int jj = 0; jj < 4; jj++) {
                int row = warp_n * 64 + jj * 16 + (lane & 7) + ((lane >> 4) & 1) * 8;
                int col = ks * 16 + ((lane >> 3) & 1) * 8;
                uint32_t t[4];
                ldsm4(t, sb + (uint32_t)(row * ASTR + col) * 2);
                bfr[jj*2][0]   = t[0]; bfr[jj*2][1]   = t[1];
                bfr[jj*2+1][0] = t[2]; bfr[jj*2+1][1] = t[3];
            }
#pragma unroll
            for (int mi = 0; mi < 2; mi++)
#pragma unroll
                for (int nj = 0; nj < 8; nj++)
                    mma_bf16(d[mi][nj], afr[mi], bfr[nj]);
        }
    }

    // ---- epilogue (section select) ----
    const int sec = gn0 / ldc;
    const int n0  = gn0 - sec * ldc;
    const float* bias = (sec == 0) ? bias0 : (sec == 1 ? bias1 : bias2);
    float* C          = (sec == 0) ? C0    : (sec == 1 ? C1    : C2);

    const int lr = lane >> 2;
    const int lc = (lane & 3) * 2;

#pragma unroll
    for (int mi = 0; mi < 2; mi++) {
        const int r0 = m0 + warp_m * 32 + mi * 16 + lr;
#pragma unroll
        for (int nj = 0; nj < 8; nj++) {
            const int c = n0 + warp_n * 64 + nj * 8 + lc;
            const float b0 = bias[c], b1 = bias[c + 1];
#pragma unroll
            for (int half = 0; half < 2; half++) {
                const int rr = r0 + half * 8;
                float v0 = d[mi][nj][half * 2 + 0] + b0;
                float v1 = d[mi][nj][half * 2 + 1] + b1;
                if (mode == 1) {
                    v0 = fmaxf(v0, 0.f); v1 = fmaxf(v1, 0.f);
                } else if (mode == 2) {
                    const float2 rv = *(const float2*)(res + (size_t)rr * ldc + c);
                    v0 += rv.x; v1 += rv.y;
                }
                *(float2*)(C + (size_t)rr * ldc + c) = make_float2(v0, v1);
                if (Chi) {
                    __nv_bfloat16 h0, l0, h1, l1;
                    split_bf16(v0, h0, l0);
                    split_bf16(v1, h1, l1);
                    *(__nv_bfloat162*)(Chi + (size_t)rr * ldc + c) = __nv_bfloat162(h0, h1);
                    *(__nv_bfloat162*)(Clo + (size_t)rr * ldc + c) = __nv_bfloat162(l0, l1);
                }
            }
        }
    }
}

// ===========================================================================
// fp32 -> (bf16 hi, bf16 lo) split converter
// ===========================================================================
__global__ __launch_bounds__(256)
void cvt_kernel(const float* __restrict__ X,
                __nv_bfloat16* __restrict__ hi, __nv_bfloat16* __restrict__ lo,
                int n)
{
    int i = (blockIdx.x * 256 + threadIdx.x) * 4;
    if (i >= n) return;
    float4 v = *(const float4*)(X + i);
    __nv_bfloat16 h0, l0, h1, l1, h2, l2, h3, l3;
    split_bf16(v.x, h0, l0); split_bf16(v.y, h1, l1);
    split_bf16(v.z, h2, l2); split_bf16(v.w, h3, l3);
    ((__nv_bfloat162*)(hi + i))[0] = __nv_bfloat162(h0, h1);
    ((__nv_bfloat162*)(hi + i))[1] = __nv_bfloat162(h2, h3);
    ((__nv_bfloat162*)(lo + i))[0] = __nv_bfloat162(l0, l1);
    ((__nv_bfloat162*)(lo + i))[1] = __nv_bfloat162(l2, l3);
}

// ===========================================================================
// Flash attention (fp32, online softmax) — also emits hi/lo bf16 split.
// ===========================================================================
#define FT  64
#define FLD 68
#define FSMEM_BYTES (4 * FT * FLD * sizeof(float))

__global__ __launch_bounds__(256, 2)
void flash_kernel(const float* __restrict__ Q,
                  const float* __restrict__ K,
                  const float* __restrict__ V,
                  float* __restrict__ O,
                  __nv_bfloat16* __restrict__ Ohi,
                  __nv_bfloat16* __restrict__ Olo,
                  int causal)
{
    extern __shared__ float fsmem[];
    float* Qs = fsmem;
    float* Ks = Qs + FT * FLD;
    float* Vs = Ks + FT * FLD;
    float* Ps = Vs + FT * FLD;

    const int tid = threadIdx.x;
    const int row = tid >> 2;
    const int cg  = tid & 3;

    const int bh = blockIdx.y;
    const int b  = bh >> 4;
    const int h  = bh & 15;
    const int q0 = blockIdx.x * FT;

    const size_t base = (size_t)b * SEQ * DM + (size_t)h * DH;
    const float* Qp = Q + base;
    const float* Kp = K + base;
    const float* Vp = V + base;

#pragma unroll
    for (int t = 0; t < 4; t++) {
        int v = tid + t * 256;
        int r = v >> 4;
        int c = (v & 15) << 2;
        float4 q4 = *(const float4*)(Qp + (size_t)(q0 + r) * DM + c);
        q4.x *= 0.125f; q4.y *= 0.125f; q4.z *= 0.125f; q4.w *= 0.125f;
        *(float4*)&Qs[r * FLD + c] = q4;
    }

    float o[16];
#pragma unroll
    for (int i = 0; i < 16; i++) o[i] = 0.f;
    float m = -1e30f, l = 0.f;

    const int ntiles = causal ? (q0 / FT + 1) : (SEQ / FT);
    for (int kt = 0; kt < ntiles; kt++) {
#pragma unroll
        for (int t = 0; t < 4; t++) {
            int v = tid + t * 256;
            int r = v >> 4;
            int c = (v & 15) << 2;
            *(float4*)&Ks[r * FLD + c] =
                *(const float4*)(Kp + (size_t)(kt * FT + r) * DM + c);
            *(float4*)&Vs[r * FLD + c] =
                *(const float4*)(Vp + (size_t)(kt * FT + r) * DM + c);
        }
        __syncthreads();

        float s[16];
        const float* qr = &Qs[row * FLD];
#pragma unroll
        for (int c = 0; c < 16; c++) {
            const float* kr = &Ks[(cg * 16 + c) * FLD];
            float acc = 0.f;
#pragma unroll
            for (int d = 0; d < DH; d += 4) {
                float4 qa = *(const float4*)(qr + d);
                float4 kb = *(const float4*)(kr + d);
                acc += qa.x * kb.x + qa.y * kb.y + qa.z * kb.z + qa.w * kb.w;
            }
            s[c] = acc;
        }
        if (causal && kt == ntiles - 1) {
            int qpos = q0 + row;
#pragma unroll
            for (int c = 0; c < 16; c++)
                if (kt * FT + cg * 16 + c > qpos) s[c] = -1e9f;
        }

        float tm = s[0];
#pragma unroll
        for (int c = 1; c < 16; c++) tm = fmaxf(tm, s[c]);
        tm = fmaxf(tm, __shfl_xor_sync(0xffffffff, tm, 1));
        tm = fmaxf(tm, __shfl_xor_sync(0xffffffff, tm, 2));
        float newm = fmaxf(m, tm);
        float corr = expf(m - newm);
        float psum = 0.f;
#pragma unroll
        for (int c = 0; c < 16; c++) {
            float p = expf(s[c] - newm);
            Ps[row * FLD + cg * 16 + c] = p;
            psum += p;
        }
        psum += __shfl_xor_sync(0xffffffff, psum, 1);
        psum += __shfl_xor_sync(0xffffffff, psum, 2);
        l = l * corr + psum;
        m = newm;
#pragma unroll
        for (int i = 0; i < 16; i++) o[i] *= corr;
        __syncthreads();

        for (int j = 0; j < FT; j++) {
            float p = Ps[row * FLD + j];
            const float4* vr = (const float4*)&Vs[j * FLD + cg * 16];
            float4 v0 = vr[0], v1 = vr[1], v2 = vr[2], v3 = vr[3];
            o[0]  += p * v0.x; o[1]  += p * v0.y; o[2]  += p * v0.z; o[3]  += p * v0.w;
            o[4]  += p * v1.x; o[5]  += p * v1.y; o[6]  += p * v1.z; o[7]  += p * v1.w;
            o[8]  += p * v2.x; o[9]  += p * v2.y; o[10] += p * v2.z; o[11] += p * v2.w;
            o[12] += p * v3.x; o[13] += p * v3.y; o[14] += p * v3.z; o[15] += p * v3.w;
        }
        __syncthreads();
    }

    const float rl = 1.f / l;
    const size_t ooff = base + (size_t)(q0 + row) * DM + cg * 16;
    float* orow = O + ooff;
#pragma unroll
    for (int i = 0; i < 16; i++) o[i] *= rl;
#pragma unroll
    for (int i = 0; i < 16; i += 4)
        *(float4*)(orow + i) = make_float4(o[i], o[i+1], o[i+2], o[i+3]);
#pragma unroll
    for (int jp = 0; jp < 8; jp++) {
        __nv_bfloat16 h0, l0, h1, l1;
        split_bf16(o[jp*2],   h0, l0);
        split_bf16(o[jp*2+1], h1, l1);
        ((__nv_bfloat162*)(Ohi + ooff))[jp] = __nv_bfloat162(h0, h1);
        ((__nv_bfloat162*)(Olo + ooff))[jp] = __nv_bfloat162(l0, l1);
    }
}

// ===========================================================================
// LayerNorm (1024), optional bf16 hi/lo split output
// ===========================================================================
__global__ __launch_bounds__(256)
void ln_kernel(const float* __restrict__ X,
               const float* __restrict__ gam,
               const float* __restrict__ bet,
               float* __restrict__ Y,
               __nv_bfloat16* __restrict__ Yhi,
               __nv_bfloat16* __restrict__ Ylo)
{
    __shared__ float red[256];
    const int row = blockIdx.x;
    const int tid = threadIdx.x;

    float4 v = ((const float4*)(X + (size_t)row * DM))[tid];

    float s = v.x + v.y + v.z + v.w;
    red[tid] = s;
    __syncthreads();
    for (int off = 128; off > 0; off >>= 1) {
        if (tid < off) red[tid] += red[tid + off];
        __syncthreads();
    }
    const float mu = red[0] * (1.f / DM);
    __syncthreads();

    float dx = v.x - mu, dy = v.y - mu, dz = v.z - mu, dw = v.w - mu;
    red[tid] = dx * dx + dy * dy + dz * dz + dw * dw;
    __syncthreads();
    for (int off = 128; off > 0; off >>= 1) {
        if (tid < off) red[tid] += red[tid + off];
        __syncthreads();
    }
    const float rstd = rsqrtf(red[0] * (1.f / DM) + LN_EPS);

    float4 g4 = ((const float4*)gam)[tid];
    float4 b4 = ((const float4*)bet)[tid];
    float4 y;
    y.x = dx * rstd * g4.x + b4.x;
    y.y = dy * rstd * g4.y + b4.y;
    y.z = dz * rstd * g4.z + b4.z;
    y.w = dw * rstd * g4.w + b4.w;
    ((float4*)(Y + (size_t)row * DM))[tid] = y;

    if (Yhi) {
        size_t off = (size_t)row * DM + tid * 4;
        __nv_bfloat16 h0, l0, h1, l1, h2, l2, h3, l3;
        split_bf16(y.x, h0, l0); split_bf16(y.y, h1, l1);
        split_bf16(y.z, h2, l2); split_bf16(y.w, h3, l3);
        ((__nv_bfloat162*)(Yhi + off))[0] = __nv_bfloat162(h0, h1);
        ((__nv_bfloat162*)(Yhi + off))[1] = __nv_bfloat162(h2, h3);
        ((__nv_bfloat162*)(Ylo + off))[0] = __nv_bfloat162(l0, l1);
        ((__nv_bfloat162*)(Ylo + off))[1] = __nv_bfloat162(l2, l3);
    }
}

// ===========================================================================
// Host orchestration
// ===========================================================================
static inline void cvt(const float* src, __nv_bfloat16* hi, __nv_bfloat16* lo,
                       size_t off, int n) {
    cvt_kernel<<<(n / 4 + 255) / 256, 256>>>(src, hi + off, lo + off, n);
}

extern "C" void kernel_launch(void* const* d_in, const int* in_sizes, int n_in,
                              void* d_out, int out_size)
{
    const float* x     = (const float*)d_in[0];
    const float* enc   = (const float*)d_in[1];
    // d_in[2] mask1 (tril), d_in[3] mask2 (ones) — structural, unused
    const float* wq1 = (const float*)d_in[4],  *bq1 = (const float*)d_in[5];
    const float* wk1 = (const float*)d_in[6],  *bk1 = (const float*)d_in[7];
    const float* wv1 = (const float*)d_in[8],  *bv1 = (const float*)d_in[9];
    const float* wo1 = (const float*)d_in[10], *bo1 = (const float*)d_in[11];
    const float* wq2 = (const float*)d_in[12], *bq2 = (const float*)d_in[13];
    const float* wk2 = (const float*)d_in[14], *bk2 = (const float*)d_in[15];
    const float* wv2 = (const float*)d_in[16], *bv2 = (const float*)d_in[17];
    const float* wo2 = (const float*)d_in[18], *bo2 = (const float*)d_in[19];
    const float* wf1 = (const float*)d_in[20], *bf1 = (const float*)d_in[21];
    const float* wf2 = (const float*)d_in[22], *bf2 = (const float*)d_in[23];
    const float* g1  = (const float*)d_in[24], *be1 = (const float*)d_in[25];
    const float* g2  = (const float*)d_in[26], *be2 = (const float*)d_in[27];
    const float* g3  = (const float*)d_in[28], *be3 = (const float*)d_in[29];
    float* out = (float*)d_out;

    float *q, *k, *v, *a, *t, *x1, *x2, *ff;
    __nv_bfloat16 *hi, *lo;
    cudaGetSymbolAddress((void**)&q,  g_q);
    cudaGetSymbolAddress((void**)&k,  g_k);
    cudaGetSymbolAddress((void**)&v,  g_v);
    cudaGetSymbolAddress((void**)&a,  g_a);
    cudaGetSymbolAddress((void**)&t,  g_t);
    cudaGetSymbolAddress((void**)&x1, g_x1);
    cudaGetSymbolAddress((void**)&x2, g_x2);
    cudaGetSymbolAddress((void**)&ff, g_ff);
    cudaGetSymbolAddress((void**)&hi, g_hi);
    cudaGetSymbolAddress((void**)&lo, g_lo);

    cudaFuncSetAttribute(flash_kernel,
                         cudaFuncAttributeMaxDynamicSharedMemorySize, (int)FSMEM_BYTES);
    cudaFuncSetAttribute(tc_gemm,
                         cudaFuncAttributeMaxDynamicSharedMemorySize, GSMEM);

    const dim3 gqkv (3 * DM / 128, MROWS / 128);   // (24, 32) merged QKV
    const dim3 gkv  (2 * DM / 128, MROWS / 128);   // (16, 32) merged KV
    const dim3 gproj(DM / 128,     MROWS / 128);   // (8, 32)
    const dim3 gff1 (DFF / 128,    MROWS / 128);   // (32, 32)
    const dim3 gfl  (SEQ / FT, BATCH * NH);

    // ---- self-attention (launch #5 is the merged QKV GEMM -> ncu target) ----
    cvt(x,   hi, lo, OFF_X,   MROWS * DM);      // 0
    cvt(wq1, hi, lo, OFF_WQ1, DM * DM);         // 1
    cvt(wk1, hi, lo, OFF_WK1, DM * DM);         // 2
    cvt(wv1, hi, lo, OFF_WV1, DM * DM);         // 3
    cvt(wo1, hi, lo, OFF_WO1, DM * DM);         // 4
    tc_gemm<<<gqkv, 256, GSMEM>>>(hi+OFF_X, lo+OFF_X, hi+OFF_WQ1, lo+OFF_WQ1,
                                  bq1, bk1, bv1, nullptr, q, k, v,
                                  nullptr, nullptr, DM, DM, 0);          // 5
    flash_kernel<<<gfl, 256, FSMEM_BYTES>>>(q, k, v, a, hi+OFF_A, lo+OFF_A, 1);
    tc_gemm<<<gproj, 256, GSMEM>>>(hi+OFF_A, lo+OFF_A, hi+OFF_WO1, lo+OFF_WO1,
                                   bo1, bo1, bo1, x, t, t, t,
                                   nullptr, nullptr, DM, DM, 2);
    ln_kernel<<<MROWS, 256>>>(t, g1, be1, x1, hi+OFF_X1, lo+OFF_X1);

    // ---- cross-attention ----
    cvt(enc, hi, lo, OFF_ENC, MROWS * DM);
    cvt(wq2, hi, lo, OFF_WQ2, DM * DM);
    cvt(wk2, hi, lo, OFF_WK2, DM * DM);
    cvt(wv2, hi, lo, OFF_WV2, DM * DM);
    cvt(wo2, hi, lo, OFF_WO2, DM * DM);
    tc_gemm<<<gproj, 256, GSMEM>>>(hi+OFF_X1, lo+OFF_X1, hi+OFF_WQ2, lo+OFF_WQ2,
                                   bq2, bq2, bq2, nullptr, q, q, q,
                                   nullptr, nullptr, DM, DM, 0);
    tc_gemm<<<gkv, 256, GSMEM>>>(hi+OFF_ENC, lo+OFF_ENC, hi+OFF_WK2, lo+OFF_WK2,
                                 bk2, bv2, bv2, nullptr, k, v, v,
                                 nullptr, nullptr, DM, DM, 0);
    flash_kernel<<<gfl, 256, FSMEM_BYTES>>>(q, k, v, a, hi+OFF_A, lo+OFF_A, 0);
    tc_gemm<<<gproj, 256, GSMEM>>>(hi+OFF_A, lo+OFF_A, hi+OFF_WO2, lo+OFF_WO2,
                                   bo2, bo2, bo2, x1, t, t, t,
                                   nullptr, nullptr, DM, DM, 2);
    ln_kernel<<<MROWS, 256>>>(t, g2, be2, x2, hi+OFF_X2, lo+OFF_X2);

    // ---- FFN ----
    cvt(wf1, hi, lo, OFF_WF1, DFF * DM);
    cvt(wf2, hi, lo, OFF_WF2, DM * DFF);
    tc_gemm<<<gff1, 256, GSMEM>>>(hi+OFF_X2, lo+OFF_X2, hi+OFF_WF1, lo+OFF_WF1,
                                  bf1, bf1, bf1, nullptr, ff, ff, ff,
                                  hi+OFF_FF, lo+OFF_FF, DM, DFF, 1);
    tc_gemm<<<gproj, 256, GSMEM>>>(hi+OFF_FF, lo+OFF_FF, hi+OFF_WF2, lo+OFF_WF2,
                                   bf2, bf2, bf2, x2, t, t, t,
                                   nullptr, nullptr, DFF, DM, 2);
    ln_kernel<<<MROWS, 256>>>(t, g3, be3, out, nullptr, nullptr);
}